// round 1
// baseline (speedup 1.0000x reference)
#include <cuda_runtime.h>
#include <cuda_bf16.h>

// Problem constants
#define SEQ 2048
#define DIM 1024
#define NHEAD 16
#define DHEAD 64
#define QKV_N (3 * DIM)   // 3072

// Scratch (device globals: allocation-free rule)
__device__ float g_qkv[SEQ * QKV_N];     // [S, 3*DIM] laid out as [s][part][h][d]
__device__ float g_attn[SEQ * DIM];      // [S, H*Dh]

// ---------------------------------------------------------------------------
// Generic tiled GEMM: C[M,N] = A[M,K] @ B[K,N] (+ bias[col] if non-null)
// 64x64 tile, BK=16, 256 threads, 4x4 register tile per thread.
// ---------------------------------------------------------------------------
__global__ __launch_bounds__(256) void gemm64(
    const float* __restrict__ A, const float* __restrict__ B,
    float* __restrict__ C, int M, int N, int K,
    const float* __restrict__ bias)
{
    __shared__ float As[16][64 + 1];
    __shared__ float Bs[16][64 + 1];

    const int tid = threadIdx.x;
    const int tx = tid & 15;        // 0..15 -> 4 output cols each
    const int ty = tid >> 4;        // 0..15 -> 4 output rows each
    const int row0 = blockIdx.y * 64;
    const int col0 = blockIdx.x * 64;

    float acc[4][4] = {};

    for (int k0 = 0; k0 < K; k0 += 16) {
        // Load A tile 64x16 into As[k][row]
        #pragma unroll
        for (int i = 0; i < 4; i++) {
            int idx = tid + i * 256;          // 0..1023
            int r = idx >> 4, c = idx & 15;
            As[c][r] = A[(size_t)(row0 + r) * K + k0 + c];
        }
        // Load B tile 16x64 into Bs[k][col]
        #pragma unroll
        for (int i = 0; i < 4; i++) {
            int idx = tid + i * 256;
            int r = idx >> 6, c = idx & 63;
            Bs[r][c] = B[(size_t)(k0 + r) * N + col0 + c];
        }
        __syncthreads();

        #pragma unroll
        for (int k = 0; k < 16; k++) {
            float a[4], b[4];
            #pragma unroll
            for (int i = 0; i < 4; i++) a[i] = As[k][ty * 4 + i];
            #pragma unroll
            for (int j = 0; j < 4; j++) b[j] = Bs[k][tx * 4 + j];
            #pragma unroll
            for (int i = 0; i < 4; i++)
                #pragma unroll
                for (int j = 0; j < 4; j++)
                    acc[i][j] = fmaf(a[i], b[j], acc[i][j]);
        }
        __syncthreads();
    }

    #pragma unroll
    for (int i = 0; i < 4; i++) {
        int r = row0 + ty * 4 + i;
        #pragma unroll
        for (int j = 0; j < 4; j++) {
            int c = col0 + tx * 4 + j;
            float v = acc[i][j];
            if (bias) v += bias[c];
            C[(size_t)r * N + c] = v;
        }
    }
}

// ---------------------------------------------------------------------------
// Flash attention (causal, online softmax).
// Grid: (SEQ/64, NHEAD). Block: 256 threads.
// Each block: one 64-query tile for one head. K/V share one smem buffer.
// smem: Qs[64][65] + KVs[64][65] + Ss[64][65] + m/l/scale[64 each]
// ---------------------------------------------------------------------------
#define ALD 65
#define ATTN_SMEM ((3 * 64 * ALD + 3 * 64) * (int)sizeof(float))

__global__ __launch_bounds__(256) void attn_kernel(
    const float* __restrict__ qkv, float* __restrict__ out)
{
    extern __shared__ float sm[];
    float* Qs  = sm;                  // 64*ALD
    float* KVs = sm + 64 * ALD;       // 64*ALD
    float* Ss  = sm + 2 * 64 * ALD;   // 64*ALD
    float* row_m     = sm + 3 * 64 * ALD;
    float* row_l     = row_m + 64;
    float* row_scale = row_l + 64;

    const int tid = threadIdx.x;
    const int tx = tid & 15;
    const int ty = tid >> 4;
    const int qb = blockIdx.x;
    const int h  = blockIdx.y;
    const int q0 = qb * 64;

    // Load Q tile: q element = qkv[(q0+r)*3072 + 0*1024 + h*64 + d]
    #pragma unroll
    for (int i = 0; i < 16; i++) {
        int idx = tid + i * 256;      // 0..4095
        int r = idx >> 6, d = idx & 63;
        Qs[r * ALD + d] = qkv[(size_t)(q0 + r) * QKV_N + h * DHEAD + d];
    }
    if (tid < 64) { row_m[tid] = -1e30f; row_l[tid] = 0.0f; }

    float o[4][4] = {};
    __syncthreads();

    for (int kt = 0; kt <= qb; kt++) {
        const int k0 = kt * 64;

        // Load K tile into KVs
        #pragma unroll
        for (int i = 0; i < 16; i++) {
            int idx = tid + i * 256;
            int r = idx >> 6, d = idx & 63;
            KVs[r * ALD + d] = qkv[(size_t)(k0 + r) * QKV_N + DIM + h * DHEAD + d];
        }
        __syncthreads();

        // S = Q K^T * scale, masked
        float s[4][4] = {};
        #pragma unroll
        for (int d = 0; d < 64; d++) {
            float a[4], b[4];
            #pragma unroll
            for (int i = 0; i < 4; i++) a[i] = Qs[(ty * 4 + i) * ALD + d];
            #pragma unroll
            for (int j = 0; j < 4; j++) b[j] = KVs[(tx * 4 + j) * ALD + d];
            #pragma unroll
            for (int i = 0; i < 4; i++)
                #pragma unroll
                for (int j = 0; j < 4; j++)
                    s[i][j] = fmaf(a[i], b[j], s[i][j]);
        }
        #pragma unroll
        for (int i = 0; i < 4; i++) {
            int qg = q0 + ty * 4 + i;
            #pragma unroll
            for (int j = 0; j < 4; j++) {
                int kg = k0 + tx * 4 + j;
                float v = s[i][j] * 0.125f;   // 1/sqrt(64)
                if (kg > qg) v = -1e30f;
                Ss[(ty * 4 + i) * ALD + tx * 4 + j] = v;
            }
        }
        __syncthreads();

        // Online softmax bookkeeping: one thread per row
        if (tid < 64) {
            int r = tid;
            float mx = -1e30f;
            #pragma unroll 8
            for (int c = 0; c < 64; c++) mx = fmaxf(mx, Ss[r * ALD + c]);
            float m_old = row_m[r];
            float m_new = fmaxf(m_old, mx);
            float sc = __expf(m_old - m_new);
            float l = row_l[r] * sc;
            #pragma unroll 8
            for (int c = 0; c < 64; c++) {
                float p = __expf(Ss[r * ALD + c] - m_new);
                Ss[r * ALD + c] = p;
                l += p;
            }
            row_m[r] = m_new;
            row_l[r] = l;
            row_scale[r] = sc;
        }
        __syncthreads();

        // Load V tile into KVs (K no longer needed)
        #pragma unroll
        for (int i = 0; i < 16; i++) {
            int idx = tid + i * 256;
            int r = idx >> 6, d = idx & 63;
            KVs[r * ALD + d] = qkv[(size_t)(k0 + r) * QKV_N + 2 * DIM + h * DHEAD + d];
        }
        __syncthreads();

        // O = O*scale + P @ V
        #pragma unroll
        for (int i = 0; i < 4; i++) {
            float sc = row_scale[ty * 4 + i];
            #pragma unroll
            for (int j = 0; j < 4; j++) o[i][j] *= sc;
        }
        #pragma unroll 8
        for (int k = 0; k < 64; k++) {
            float p[4], v[4];
            #pragma unroll
            for (int i = 0; i < 4; i++) p[i] = Ss[(ty * 4 + i) * ALD + k];
            #pragma unroll
            for (int j = 0; j < 4; j++) v[j] = KVs[k * ALD + tx * 4 + j];
            #pragma unroll
            for (int i = 0; i < 4; i++)
                #pragma unroll
                for (int j = 0; j < 4; j++)
                    o[i][j] = fmaf(p[i], v[j], o[i][j]);
        }
        __syncthreads();
    }

    // Epilogue: normalize and write [q, h*64 + d]
    #pragma unroll
    for (int i = 0; i < 4; i++) {
        float inv = 1.0f / row_l[ty * 4 + i];
        #pragma unroll
        for (int j = 0; j < 4; j++) {
            out[(size_t)(q0 + ty * 4 + i) * DIM + h * DHEAD + tx * 4 + j] = o[i][j] * inv;
        }
    }
}

// ---------------------------------------------------------------------------
// Launch
// ---------------------------------------------------------------------------
extern "C" void kernel_launch(void* const* d_in, const int* in_sizes, int n_in,
                              void* d_out, int out_size)
{
    const float* x    = (const float*)d_in[0];
    const float* Wqkv = (const float*)d_in[1];
    const float* Wout = (const float*)d_in[2];
    const float* bias = (const float*)d_in[3];
    float* out = (float*)d_out;

    float *qkv_ptr, *attn_ptr;
    cudaGetSymbolAddress((void**)&qkv_ptr,  g_qkv);
    cudaGetSymbolAddress((void**)&attn_ptr, g_attn);

    // Opt-in to >48KB dynamic smem for the attention kernel (idempotent).
    cudaFuncSetAttribute(attn_kernel, cudaFuncAttributeMaxDynamicSharedMemorySize,
                         ATTN_SMEM);

    dim3 blk(256);

    // 1) qkv = x @ Wqkv   [2048, 3072]
    gemm64<<<dim3(QKV_N / 64, SEQ / 64), blk>>>(x, Wqkv, qkv_ptr,
                                                SEQ, QKV_N, DIM, nullptr);

    // 2) flash attention -> g_attn [2048, 1024]
    attn_kernel<<<dim3(SEQ / 64, NHEAD), blk, ATTN_SMEM>>>(qkv_ptr, attn_ptr);

    // 3) out = attn @ Wout + bias  [2048, 1024]
    gemm64<<<dim3(DIM / 64, SEQ / 64), blk>>>(attn_ptr, Wout, out,
                                              SEQ, DIM, DIM, bias);
}

// round 2
// speedup vs baseline: 1.4155x; 1.4155x over previous
#include <cuda_runtime.h>
#include <cuda_bf16.h>

#define SEQ 2048
#define DIM 1024
#define NHEAD 16
#define DHEAD 64
#define QKV_N (3 * DIM)   // 3072

__device__ float g_qkv[SEQ * QKV_N];
__device__ float g_attn[SEQ * DIM];

// ---------------------------------------------------------------------------
// SGEMM: C[M,N] = A[M,K] @ B[K,N] (+bias). 128x128 tile, BK=8, 256 threads,
// 8x8 register tile, double-buffered smem, float4 everywhere.
// ---------------------------------------------------------------------------
#define BM 128
#define BN 128
#define BK 8

__global__ __launch_bounds__(256) void sgemm(
    const float* __restrict__ A, const float* __restrict__ B,
    float* __restrict__ C, int M, int N, int K,
    const float* __restrict__ bias)
{
    __shared__ float As[2][BK][BM];
    __shared__ float Bs[2][BK][BN];

    const int tid  = threadIdx.x;
    const int row0 = blockIdx.y * BM;
    const int col0 = blockIdx.x * BN;

    // A loader: 128 rows x 8 cols = 256 float4 (2 per row along K)
    const int a_row = tid >> 1;
    const int a_col = (tid & 1) * 4;
    // B loader: 8 rows x 128 cols = 256 float4 (32 per row along N)
    const int b_row = tid >> 5;
    const int b_col = (tid & 31) * 4;

    const float* Aptr = A + (size_t)(row0 + a_row) * K + a_col;
    const float* Bptr = B + (size_t)b_row * N + col0 + b_col;

    // Compute-thread mapping: 16x16 threads, each owns 8x8
    const int tr = (tid >> 4) * 8;
    const int tc = (tid & 15) * 8;

    float acc[8][8] = {};

    // Prefetch tile 0
    float4 a_reg = *(const float4*)(Aptr);
    float4 b_reg = *(const float4*)(Bptr);
    As[0][a_col + 0][a_row] = a_reg.x;
    As[0][a_col + 1][a_row] = a_reg.y;
    As[0][a_col + 2][a_row] = a_reg.z;
    As[0][a_col + 3][a_row] = a_reg.w;
    *(float4*)&Bs[0][b_row][b_col] = b_reg;
    __syncthreads();

    int buf = 0;
    for (int k0 = BK; k0 <= K; k0 += BK) {
        // Prefetch next tile into registers
        if (k0 < K) {
            a_reg = *(const float4*)(Aptr + k0);
            b_reg = *(const float4*)(Bptr + (size_t)k0 * N);
        }

        // Compute current buffer
        #pragma unroll
        for (int k = 0; k < BK; k++) {
            float a[8], b[8];
            *(float4*)(a)     = *(float4*)&As[buf][k][tr];
            *(float4*)(a + 4) = *(float4*)&As[buf][k][tr + 4];
            *(float4*)(b)     = *(float4*)&Bs[buf][k][tc];
            *(float4*)(b + 4) = *(float4*)&Bs[buf][k][tc + 4];
            #pragma unroll
            for (int i = 0; i < 8; i++)
                #pragma unroll
                for (int j = 0; j < 8; j++)
                    acc[i][j] = fmaf(a[i], b[j], acc[i][j]);
        }

        // Store prefetch into alternate buffer
        if (k0 < K) {
            int nb = buf ^ 1;
            As[nb][a_col + 0][a_row] = a_reg.x;
            As[nb][a_col + 1][a_row] = a_reg.y;
            As[nb][a_col + 2][a_row] = a_reg.z;
            As[nb][a_col + 3][a_row] = a_reg.w;
            *(float4*)&Bs[nb][b_row][b_col] = b_reg;
        }
        __syncthreads();
        buf ^= 1;
    }

    // Epilogue
    #pragma unroll
    for (int i = 0; i < 8; i++) {
        int r = row0 + tr + i;
        #pragma unroll
        for (int j4 = 0; j4 < 8; j4 += 4) {
            int c = col0 + tc + j4;
            float4 v = make_float4(acc[i][j4], acc[i][j4+1], acc[i][j4+2], acc[i][j4+3]);
            if (bias) {
                v.x += bias[c]; v.y += bias[c+1]; v.z += bias[c+2]; v.w += bias[c+3];
            }
            *(float4*)&C[(size_t)r * N + c] = v;
        }
    }
}

// ---------------------------------------------------------------------------
// Flash attention, 64 queries x 64 keys per tile, 256 threads, register-
// resident online softmax with 16-lane shuffle reductions.
// Q,K stored transposed [d][row] for vectorized QK^T; V,P row-major.
// ---------------------------------------------------------------------------
#define QLD 68
#define ATTN_SMEM (4 * 64 * QLD * (int)sizeof(float))

__global__ __launch_bounds__(256) void attn_kernel(
    const float* __restrict__ qkv, float* __restrict__ out)
{
    extern __shared__ float sm[];
    float* Qt = sm;               // [64][QLD] : Qt[d][r]  (pre-scaled)
    float* Kt = Qt + 64 * QLD;    // [64][QLD] : Kt[d][r]
    float* Vs = Kt + 64 * QLD;    // [64][QLD] : Vs[r][d]
    float* Ss = Vs + 64 * QLD;    // [64][QLD] : Ss[r][c]

    const int tid = threadIdx.x;
    const int tx  = tid & 15;
    const int ty  = tid >> 4;
    const int qb  = blockIdx.x;
    const int h   = blockIdx.y;
    const int q0  = qb * 64;

    // Load Q (transposed + scaled by 1/sqrt(64))
    #pragma unroll
    for (int i = 0; i < 4; i++) {
        int idx = tid + i * 256;
        int r = idx >> 4, d4 = (idx & 15) * 4;
        float4 v = *(const float4*)(qkv + (size_t)(q0 + r) * QKV_N + h * DHEAD + d4);
        Qt[(d4 + 0) * QLD + r] = v.x * 0.125f;
        Qt[(d4 + 1) * QLD + r] = v.y * 0.125f;
        Qt[(d4 + 2) * QLD + r] = v.z * 0.125f;
        Qt[(d4 + 3) * QLD + r] = v.w * 0.125f;
    }

    float o[4][4] = {};
    float m_i[4] = {-1e30f, -1e30f, -1e30f, -1e30f};
    float l_i[4] = {};

    for (int kt = 0; kt <= qb; kt++) {
        const int k0 = kt * 64;

        // Load K (transposed) and V (row-major)
        #pragma unroll
        for (int i = 0; i < 4; i++) {
            int idx = tid + i * 256;
            int r = idx >> 4, d4 = (idx & 15) * 4;
            const float* kp = qkv + (size_t)(k0 + r) * QKV_N + DIM + h * DHEAD + d4;
            float4 kv = *(const float4*)kp;
            Kt[(d4 + 0) * QLD + r] = kv.x;
            Kt[(d4 + 1) * QLD + r] = kv.y;
            Kt[(d4 + 2) * QLD + r] = kv.z;
            Kt[(d4 + 3) * QLD + r] = kv.w;
            *(float4*)&Vs[r * QLD + d4] = *(const float4*)(kp + DIM);
        }
        __syncthreads();

        // S = Q K^T (already scaled via Q)
        float s[4][4] = {};
        #pragma unroll
        for (int d = 0; d < 64; d++) {
            float4 a = *(float4*)&Qt[d * QLD + ty * 4];
            float4 b = *(float4*)&Kt[d * QLD + tx * 4];
            s[0][0] = fmaf(a.x, b.x, s[0][0]); s[0][1] = fmaf(a.x, b.y, s[0][1]);
            s[0][2] = fmaf(a.x, b.z, s[0][2]); s[0][3] = fmaf(a.x, b.w, s[0][3]);
            s[1][0] = fmaf(a.y, b.x, s[1][0]); s[1][1] = fmaf(a.y, b.y, s[1][1]);
            s[1][2] = fmaf(a.y, b.z, s[1][2]); s[1][3] = fmaf(a.y, b.w, s[1][3]);
            s[2][0] = fmaf(a.z, b.x, s[2][0]); s[2][1] = fmaf(a.z, b.y, s[2][1]);
            s[2][2] = fmaf(a.z, b.z, s[2][2]); s[2][3] = fmaf(a.z, b.w, s[2][3]);
            s[3][0] = fmaf(a.w, b.x, s[3][0]); s[3][1] = fmaf(a.w, b.y, s[3][1]);
            s[3][2] = fmaf(a.w, b.z, s[3][2]); s[3][3] = fmaf(a.w, b.w, s[3][3]);
        }

        // Causal mask: only the diagonal tile has masked entries
        if (kt == qb) {
            #pragma unroll
            for (int i = 0; i < 4; i++) {
                int qg = ty * 4 + i;
                #pragma unroll
                for (int j = 0; j < 4; j++)
                    if (tx * 4 + j > qg) s[i][j] = -1e30f;
            }
        }

        // Online softmax, per row (4 rows per thread), reduce across 16 tx lanes
        #pragma unroll
        for (int i = 0; i < 4; i++) {
            float mx = fmaxf(fmaxf(s[i][0], s[i][1]), fmaxf(s[i][2], s[i][3]));
            #pragma unroll
            for (int off = 8; off > 0; off >>= 1)
                mx = fmaxf(mx, __shfl_xor_sync(0xffffffffu, mx, off));
            float m_new = fmaxf(m_i[i], mx);
            float sc = __expf(m_i[i] - m_new);
            float lsum = 0.0f;
            #pragma unroll
            for (int j = 0; j < 4; j++) {
                float p = __expf(s[i][j] - m_new);
                s[i][j] = p;
                lsum += p;
            }
            #pragma unroll
            for (int off = 8; off > 0; off >>= 1)
                lsum += __shfl_xor_sync(0xffffffffu, lsum, off);
            l_i[i] = l_i[i] * sc + lsum;
            m_i[i] = m_new;
            o[i][0] *= sc; o[i][1] *= sc; o[i][2] *= sc; o[i][3] *= sc;
        }

        // Write P to smem
        #pragma unroll
        for (int i = 0; i < 4; i++)
            *(float4*)&Ss[(ty * 4 + i) * QLD + tx * 4] =
                make_float4(s[i][0], s[i][1], s[i][2], s[i][3]);
        __syncthreads();

        // O += P @ V  (vectorized over 4 k at a time)
        #pragma unroll
        for (int k4 = 0; k4 < 64; k4 += 4) {
            float4 v0 = *(float4*)&Vs[(k4 + 0) * QLD + tx * 4];
            float4 v1 = *(float4*)&Vs[(k4 + 1) * QLD + tx * 4];
            float4 v2 = *(float4*)&Vs[(k4 + 2) * QLD + tx * 4];
            float4 v3 = *(float4*)&Vs[(k4 + 3) * QLD + tx * 4];
            #pragma unroll
            for (int i = 0; i < 4; i++) {
                float4 p = *(float4*)&Ss[(ty * 4 + i) * QLD + k4];
                o[i][0] = fmaf(p.x, v0.x, fmaf(p.y, v1.x, fmaf(p.z, v2.x, fmaf(p.w, v3.x, o[i][0]))));
                o[i][1] = fmaf(p.x, v0.y, fmaf(p.y, v1.y, fmaf(p.z, v2.y, fmaf(p.w, v3.y, o[i][1]))));
                o[i][2] = fmaf(p.x, v0.z, fmaf(p.y, v1.z, fmaf(p.z, v2.z, fmaf(p.w, v3.z, o[i][2]))));
                o[i][3] = fmaf(p.x, v0.w, fmaf(p.y, v1.w, fmaf(p.z, v2.w, fmaf(p.w, v3.w, o[i][3]))));
            }
        }
        __syncthreads();
    }

    // Epilogue: normalize, write out[q][h*64+d]
    #pragma unroll
    for (int i = 0; i < 4; i++) {
        float inv = 1.0f / l_i[i];
        float4 v = make_float4(o[i][0] * inv, o[i][1] * inv, o[i][2] * inv, o[i][3] * inv);
        *(float4*)&out[(size_t)(q0 + ty * 4 + i) * DIM + h * DHEAD + tx * 4] = v;
    }
}

// ---------------------------------------------------------------------------
extern "C" void kernel_launch(void* const* d_in, const int* in_sizes, int n_in,
                              void* d_out, int out_size)
{
    const float* x    = (const float*)d_in[0];
    const float* Wqkv = (const float*)d_in[1];
    const float* Wout = (const float*)d_in[2];
    const float* bias = (const float*)d_in[3];
    float* out = (float*)d_out;

    float *qkv_ptr, *attn_ptr;
    cudaGetSymbolAddress((void**)&qkv_ptr,  g_qkv);
    cudaGetSymbolAddress((void**)&attn_ptr, g_attn);

    cudaFuncSetAttribute(attn_kernel, cudaFuncAttributeMaxDynamicSharedMemorySize,
                         ATTN_SMEM);

    dim3 blk(256);

    sgemm<<<dim3(QKV_N / BN, SEQ / BM), blk>>>(x, Wqkv, qkv_ptr,
                                               SEQ, QKV_N, DIM, nullptr);

    attn_kernel<<<dim3(SEQ / 64, NHEAD), blk, ATTN_SMEM>>>(qkv_ptr, attn_ptr);

    sgemm<<<dim3(DIM / BN, SEQ / BM), blk>>>(attn_ptr, Wout, out,
                                             SEQ, DIM, DIM, bias);
}

// round 4
// speedup vs baseline: 2.1114x; 1.4917x over previous
#include <cuda_runtime.h>
#include <cuda_bf16.h>
#include <cstdint>

#define SEQ 2048
#define DIM 1024
#define NHEAD 16
#define DHEAD 64
#define QKV_N (3 * DIM)   // 3072

// ---------------------------------------------------------------------------
// Scratch (device globals — allocation-free rule)
// ---------------------------------------------------------------------------
__device__ float g_qkv[SEQ * QKV_N];
__device__ float g_attn[SEQ * DIM];
__device__ __nv_bfloat16 g_x_hi[SEQ * DIM];
__device__ __nv_bfloat16 g_x_lo[SEQ * DIM];
__device__ __nv_bfloat16 g_wqkv_hi[QKV_N * DIM];   // [N,K] transposed
__device__ __nv_bfloat16 g_wqkv_lo[QKV_N * DIM];
__device__ __nv_bfloat16 g_wout_hi[DIM * DIM];     // [N,K] transposed
__device__ __nv_bfloat16 g_wout_lo[DIM * DIM];
__device__ __nv_bfloat16 g_attn_hi[SEQ * DIM];
__device__ __nv_bfloat16 g_attn_lo[SEQ * DIM];

// ---------------------------------------------------------------------------
// PTX helpers (all baseline sm_80+ features: mma.sync / ldmatrix / cp.async)
// ---------------------------------------------------------------------------
__device__ __forceinline__ uint32_t smem_u32(const void* p) {
    uint32_t a;
    asm("{ .reg .u64 t; cvta.to.shared.u64 t, %1; cvt.u32.u64 %0, t; }"
        : "=r"(a) : "l"(p));
    return a;
}

__device__ __forceinline__ void ldsm_x4(uint32_t* r, uint32_t addr) {
    asm volatile("ldmatrix.sync.aligned.m8n8.x4.shared.b16 {%0,%1,%2,%3}, [%4];"
                 : "=r"(r[0]), "=r"(r[1]), "=r"(r[2]), "=r"(r[3]) : "r"(addr));
}

__device__ __forceinline__ void mma_bf16(float* d, const uint32_t* a,
                                         const uint32_t* b) {
    asm volatile(
        "mma.sync.aligned.m16n8k16.row.col.f32.bf16.bf16.f32 "
        "{%0,%1,%2,%3}, {%4,%5,%6,%7}, {%8,%9}, {%0,%1,%2,%3};"
        : "+f"(d[0]), "+f"(d[1]), "+f"(d[2]), "+f"(d[3])
        : "r"(a[0]), "r"(a[1]), "r"(a[2]), "r"(a[3]), "r"(b[0]), "r"(b[1]));
}

__device__ __forceinline__ void cp16(uint32_t dst, const void* src) {
    asm volatile("cp.async.cg.shared.global [%0], [%1], 16;"
                 :: "r"(dst), "l"(src));
}
#define CP_WAIT_ALL() asm volatile("cp.async.wait_all;" ::: "memory")

// swizzled smem byte offset for (row, 16B-seg) in a 128B-row tile
#define SWZ(r, seg) ((uint32_t)((r) * 128 + (((seg) ^ ((r) & 7)) << 4)))

// ---------------------------------------------------------------------------
// Elementwise split: fp32 -> bf16 hi + bf16 lo  (x ~ hi + lo)
// ---------------------------------------------------------------------------
__global__ __launch_bounds__(256) void split_kernel(
    const float* __restrict__ in,
    __nv_bfloat16* __restrict__ hi, __nv_bfloat16* __restrict__ lo)
{
    int i = (blockIdx.x * 256 + threadIdx.x) * 4;
    float4 v = *(const float4*)(in + i);
    __nv_bfloat16 h0 = __float2bfloat16(v.x);
    __nv_bfloat16 h1 = __float2bfloat16(v.y);
    __nv_bfloat16 h2 = __float2bfloat16(v.z);
    __nv_bfloat16 h3 = __float2bfloat16(v.w);
    *(__nv_bfloat162*)(hi + i)     = __nv_bfloat162(h0, h1);
    *(__nv_bfloat162*)(hi + i + 2) = __nv_bfloat162(h2, h3);
    *(__nv_bfloat162*)(lo + i) = __nv_bfloat162(
        __float2bfloat16(v.x - __bfloat162float(h0)),
        __float2bfloat16(v.y - __bfloat162float(h1)));
    *(__nv_bfloat162*)(lo + i + 2) = __nv_bfloat162(
        __float2bfloat16(v.z - __bfloat162float(h2)),
        __float2bfloat16(v.w - __bfloat162float(h3)));
}

// ---------------------------------------------------------------------------
// Transpose + split: W[K,N] fp32 -> Wt[N,K] bf16 hi/lo. 32x32 tiles.
// ---------------------------------------------------------------------------
__global__ __launch_bounds__(256) void tsplit_kernel(
    const float* __restrict__ W,
    __nv_bfloat16* __restrict__ hi, __nv_bfloat16* __restrict__ lo,
    int K, int N)
{
    __shared__ float t[32][33];
    const int n0 = blockIdx.x * 32, k0 = blockIdx.y * 32;
    const int tx = threadIdx.x, ty = threadIdx.y;   // 32 x 8

    #pragma unroll
    for (int j = 0; j < 4; j++)
        t[ty + 8 * j][tx] = W[(size_t)(k0 + ty + 8 * j) * N + n0 + tx];
    __syncthreads();

    #pragma unroll
    for (int j = 0; j < 4; j++) {
        int row = ty + 8 * j;                 // local n
        float v = t[tx][row];                 // = W[k0+tx][n0+row]
        __nv_bfloat16 h = __float2bfloat16(v);
        size_t o = (size_t)(n0 + row) * K + k0 + tx;
        hi[o] = h;
        lo[o] = __float2bfloat16(v - __bfloat162float(h));
    }
}

// ---------------------------------------------------------------------------
// Split-bf16 tensor-core GEMM via mma.sync:
//   C[M,N] = A[M,K] @ Bt[N,K]^T (+bias),  A,B given as hi/lo bf16 pairs.
// CTA: 128x128 tile, K-chunks of 64. smem 4x16KB (Ahi,Alo,Bhi,Blo), SWZ128.
// 8 warps (4x2), each 32x64: 2 m-tiles x 8 n-tiles of m16n8k16.
// 3 MMA terms: AhiBhi + AhiBlo + AloBhi  (fp32 accum -> ~1e-5 rel err).
// ---------------------------------------------------------------------------
#define G_SMEM (4 * 16384)

__global__ __launch_bounds__(256, 2) void gemm_mma(
    const __nv_bfloat16* __restrict__ Ahi, const __nv_bfloat16* __restrict__ Alo,
    const __nv_bfloat16* __restrict__ Bhi, const __nv_bfloat16* __restrict__ Blo,
    float* __restrict__ C, int Mtot, int Ntot, int Ktot,
    const float* __restrict__ bias)
{
    extern __shared__ char smem[];
    const uint32_t sb = smem_u32(smem);
    const int tid  = threadIdx.x;
    const int wid  = tid >> 5;
    const int lane = tid & 31;
    const int row0 = blockIdx.y * 128, col0 = blockIdx.x * 128;

    const int m0 = (wid & 3) * 32;     // warp row offset in tile
    const int n0 = (wid >> 2) * 64;    // warp col offset in tile

    const uint32_t sA  = sb;
    const uint32_t sAL = sb + 16384;
    const uint32_t sB  = sb + 32768;
    const uint32_t sBL = sb + 49152;

    float acc[2][8][4] = {};

    const int nchunks = Ktot >> 6;
    for (int c = 0; c < nchunks; c++) {
        // g2s: 4 tiles x 128 rows x 64 bf16, 16B per cp.async
        #pragma unroll
        for (int i = 0; i < 16; i++) {
            const int tile = i >> 2;
            int idx = tid + i * 256;
            int r   = (idx >> 3) & 127;
            int seg = idx & 7;
            const __nv_bfloat16* src;
            if (tile == 0)      src = Ahi + (size_t)(row0 + r) * Ktot;
            else if (tile == 1) src = Alo + (size_t)(row0 + r) * Ktot;
            else if (tile == 2) src = Bhi + (size_t)(col0 + r) * Ktot;
            else                src = Blo + (size_t)(col0 + r) * Ktot;
            cp16(sb + tile * 16384 + SWZ(r, seg), src + c * 64 + seg * 8);
        }
        CP_WAIT_ALL();
        __syncthreads();

        #pragma unroll
        for (int ks = 0; ks < 4; ks++) {
            // A fragments (hi & lo), 2 m-tiles
            uint32_t aH[2][4], aL[2][4];
            #pragma unroll
            for (int mt = 0; mt < 2; mt++) {
                int r   = m0 + mt * 16 + (lane & 15);
                int seg = ks * 2 + (lane >> 4);
                uint32_t off = SWZ(r, seg);
                ldsm_x4(aH[mt], sA  + off);
                ldsm_x4(aL[mt], sAL + off);
            }
            // B fragment pairs; 4 pairs cover 8 n-tiles
            #pragma unroll
            for (int np = 0; np < 4; np++) {
                int nr  = n0 + np * 16 + ((lane >> 4) << 3) + (lane & 7);
                int seg = ks * 2 + ((lane >> 3) & 1);
                uint32_t off = SWZ(nr, seg);
                uint32_t bH[4], bL[4];
                ldsm_x4(bH, sB  + off);
                ldsm_x4(bL, sBL + off);
                #pragma unroll
                for (int mt = 0; mt < 2; mt++) {
                    mma_bf16(acc[mt][np * 2],     aH[mt], bH);
                    mma_bf16(acc[mt][np * 2 + 1], aH[mt], bH + 2);
                    mma_bf16(acc[mt][np * 2],     aH[mt], bL);
                    mma_bf16(acc[mt][np * 2 + 1], aH[mt], bL + 2);
                    mma_bf16(acc[mt][np * 2],     aL[mt], bH);
                    mma_bf16(acc[mt][np * 2 + 1], aL[mt], bH + 2);
                }
            }
        }
        __syncthreads();
    }

    // Epilogue: write accumulators (+bias)
    #pragma unroll
    for (int mt = 0; mt < 2; mt++) {
        int r = row0 + m0 + mt * 16 + (lane >> 2);
        #pragma unroll
        for (int nt = 0; nt < 8; nt++) {
            int cc = col0 + n0 + nt * 8 + (lane & 3) * 2;
            float bx = 0.f, by = 0.f;
            if (bias) { bx = bias[cc]; by = bias[cc + 1]; }
            float2 v0 = make_float2(acc[mt][nt][0] + bx, acc[mt][nt][1] + by);
            float2 v1 = make_float2(acc[mt][nt][2] + bx, acc[mt][nt][3] + by);
            *(float2*)&C[(size_t)r * Ntot + cc]       = v0;
            *(float2*)&C[(size_t)(r + 8) * Ntot + cc] = v1;
        }
    }
}

// ---------------------------------------------------------------------------
// Flash attention (fp32 SIMT, as in R2 — converted to mma.sync next round)
// ---------------------------------------------------------------------------
#define QLD 68
#define ATTN_SMEM (4 * 64 * QLD * (int)sizeof(float))

__global__ __launch_bounds__(256) void attn_kernel(
    const float* __restrict__ qkv, float* __restrict__ out)
{
    extern __shared__ float sm[];
    float* Qt = sm;
    float* Kt = Qt + 64 * QLD;
    float* Vs = Kt + 64 * QLD;
    float* Ss = Vs + 64 * QLD;

    const int tid = threadIdx.x;
    const int tx  = tid & 15;
    const int ty  = tid >> 4;
    const int qb  = blockIdx.x;
    const int h   = blockIdx.y;
    const int q0  = qb * 64;

    #pragma unroll
    for (int i = 0; i < 4; i++) {
        int idx = tid + i * 256;
        int r = idx >> 4, d4 = (idx & 15) * 4;
        float4 v = *(const float4*)(qkv + (size_t)(q0 + r) * QKV_N + h * DHEAD + d4);
        Qt[(d4 + 0) * QLD + r] = v.x * 0.125f;
        Qt[(d4 + 1) * QLD + r] = v.y * 0.125f;
        Qt[(d4 + 2) * QLD + r] = v.z * 0.125f;
        Qt[(d4 + 3) * QLD + r] = v.w * 0.125f;
    }

    float o[4][4] = {};
    float m_i[4] = {-1e30f, -1e30f, -1e30f, -1e30f};
    float l_i[4] = {};

    for (int kt = 0; kt <= qb; kt++) {
        const int k0 = kt * 64;

        #pragma unroll
        for (int i = 0; i < 4; i++) {
            int idx = tid + i * 256;
            int r = idx >> 4, d4 = (idx & 15) * 4;
            const float* kp = qkv + (size_t)(k0 + r) * QKV_N + DIM + h * DHEAD + d4;
            float4 kv = *(const float4*)kp;
            Kt[(d4 + 0) * QLD + r] = kv.x;
            Kt[(d4 + 1) * QLD + r] = kv.y;
            Kt[(d4 + 2) * QLD + r] = kv.z;
            Kt[(d4 + 3) * QLD + r] = kv.w;
            *(float4*)&Vs[r * QLD + d4] = *(const float4*)(kp + DIM);
        }
        __syncthreads();

        float s[4][4] = {};
        #pragma unroll
        for (int d = 0; d < 64; d++) {
            float4 a = *(float4*)&Qt[d * QLD + ty * 4];
            float4 b = *(float4*)&Kt[d * QLD + tx * 4];
            s[0][0] = fmaf(a.x, b.x, s[0][0]); s[0][1] = fmaf(a.x, b.y, s[0][1]);
            s[0][2] = fmaf(a.x, b.z, s[0][2]); s[0][3] = fmaf(a.x, b.w, s[0][3]);
            s[1][0] = fmaf(a.y, b.x, s[1][0]); s[1][1] = fmaf(a.y, b.y, s[1][1]);
            s[1][2] = fmaf(a.y, b.z, s[1][2]); s[1][3] = fmaf(a.y, b.w, s[1][3]);
            s[2][0] = fmaf(a.z, b.x, s[2][0]); s[2][1] = fmaf(a.z, b.y, s[2][1]);
            s[2][2] = fmaf(a.z, b.z, s[2][2]); s[2][3] = fmaf(a.z, b.w, s[2][3]);
            s[3][0] = fmaf(a.w, b.x, s[3][0]); s[3][1] = fmaf(a.w, b.y, s[3][1]);
            s[3][2] = fmaf(a.w, b.z, s[3][2]); s[3][3] = fmaf(a.w, b.w, s[3][3]);
        }

        if (kt == qb) {
            #pragma unroll
            for (int i = 0; i < 4; i++) {
                int qg = ty * 4 + i;
                #pragma unroll
                for (int j = 0; j < 4; j++)
                    if (tx * 4 + j > qg) s[i][j] = -1e30f;
            }
        }

        #pragma unroll
        for (int i = 0; i < 4; i++) {
            float mx = fmaxf(fmaxf(s[i][0], s[i][1]), fmaxf(s[i][2], s[i][3]));
            #pragma unroll
            for (int off = 8; off > 0; off >>= 1)
                mx = fmaxf(mx, __shfl_xor_sync(0xffffffffu, mx, off));
            float m_new = fmaxf(m_i[i], mx);
            float sc = __expf(m_i[i] - m_new);
            float lsum = 0.0f;
            #pragma unroll
            for (int j = 0; j < 4; j++) {
                float p = __expf(s[i][j] - m_new);
                s[i][j] = p;
                lsum += p;
            }
            #pragma unroll
            for (int off = 8; off > 0; off >>= 1)
                lsum += __shfl_xor_sync(0xffffffffu, lsum, off);
            l_i[i] = l_i[i] * sc + lsum;
            m_i[i] = m_new;
            o[i][0] *= sc; o[i][1] *= sc; o[i][2] *= sc; o[i][3] *= sc;
        }

        #pragma unroll
        for (int i = 0; i < 4; i++)
            *(float4*)&Ss[(ty * 4 + i) * QLD + tx * 4] =
                make_float4(s[i][0], s[i][1], s[i][2], s[i][3]);
        __syncthreads();

        #pragma unroll
        for (int k4 = 0; k4 < 64; k4 += 4) {
            float4 v0 = *(float4*)&Vs[(k4 + 0) * QLD + tx * 4];
            float4 v1 = *(float4*)&Vs[(k4 + 1) * QLD + tx * 4];
            float4 v2 = *(float4*)&Vs[(k4 + 2) * QLD + tx * 4];
            float4 v3 = *(float4*)&Vs[(k4 + 3) * QLD + tx * 4];
            #pragma unroll
            for (int i = 0; i < 4; i++) {
                float4 p = *(float4*)&Ss[(ty * 4 + i) * QLD + k4];
                o[i][0] = fmaf(p.x, v0.x, fmaf(p.y, v1.x, fmaf(p.z, v2.x, fmaf(p.w, v3.x, o[i][0]))));
                o[i][1] = fmaf(p.x, v0.y, fmaf(p.y, v1.y, fmaf(p.z, v2.y, fmaf(p.w, v3.y, o[i][1]))));
                o[i][2] = fmaf(p.x, v0.z, fmaf(p.y, v1.z, fmaf(p.z, v2.z, fmaf(p.w, v3.z, o[i][2]))));
                o[i][3] = fmaf(p.x, v0.w, fmaf(p.y, v1.w, fmaf(p.z, v2.w, fmaf(p.w, v3.w, o[i][3]))));
            }
        }
        __syncthreads();
    }

    #pragma unroll
    for (int i = 0; i < 4; i++) {
        float inv = 1.0f / l_i[i];
        float4 v = make_float4(o[i][0] * inv, o[i][1] * inv, o[i][2] * inv, o[i][3] * inv);
        *(float4*)&out[(size_t)(q0 + ty * 4 + i) * DIM + h * DHEAD + tx * 4] = v;
    }
}

// ---------------------------------------------------------------------------
extern "C" void kernel_launch(void* const* d_in, const int* in_sizes, int n_in,
                              void* d_out, int out_size)
{
    const float* x    = (const float*)d_in[0];
    const float* Wqkv = (const float*)d_in[1];
    const float* Wout = (const float*)d_in[2];
    const float* bias = (const float*)d_in[3];
    float* out = (float*)d_out;

    float *qkv_p, *attn_p;
    __nv_bfloat16 *xh, *xl, *wqh, *wql, *woh, *wol, *ah, *al;
    cudaGetSymbolAddress((void**)&qkv_p,  g_qkv);
    cudaGetSymbolAddress((void**)&attn_p, g_attn);
    cudaGetSymbolAddress((void**)&xh,  g_x_hi);
    cudaGetSymbolAddress((void**)&xl,  g_x_lo);
    cudaGetSymbolAddress((void**)&wqh, g_wqkv_hi);
    cudaGetSymbolAddress((void**)&wql, g_wqkv_lo);
    cudaGetSymbolAddress((void**)&woh, g_wout_hi);
    cudaGetSymbolAddress((void**)&wol, g_wout_lo);
    cudaGetSymbolAddress((void**)&ah,  g_attn_hi);
    cudaGetSymbolAddress((void**)&al,  g_attn_lo);

    cudaFuncSetAttribute(attn_kernel, cudaFuncAttributeMaxDynamicSharedMemorySize,
                         ATTN_SMEM);
    cudaFuncSetAttribute(gemm_mma, cudaFuncAttributeMaxDynamicSharedMemorySize,
                         G_SMEM);

    // Prep: split x, transpose+split weights
    split_kernel<<<SEQ * DIM / 1024, 256>>>(x, xh, xl);
    tsplit_kernel<<<dim3(QKV_N / 32, DIM / 32), dim3(32, 8)>>>(Wqkv, wqh, wql,
                                                               DIM, QKV_N);
    tsplit_kernel<<<dim3(DIM / 32, DIM / 32), dim3(32, 8)>>>(Wout, woh, wol,
                                                             DIM, DIM);

    // 1) qkv = x @ Wqkv
    gemm_mma<<<dim3(QKV_N / 128, SEQ / 128), 256, G_SMEM>>>(
        xh, xl, wqh, wql, qkv_p, SEQ, QKV_N, DIM, nullptr);

    // 2) attention
    attn_kernel<<<dim3(SEQ / 64, NHEAD), 256, ATTN_SMEM>>>(qkv_p, attn_p);

    // 3) split attn, out = attn @ Wout + bias
    split_kernel<<<SEQ * DIM / 1024, 256>>>(attn_p, ah, al);
    gemm_mma<<<dim3(DIM / 128, SEQ / 128), 256, G_SMEM>>>(
        ah, al, woh, wol, out, SEQ, DIM, DIM, bias);
}

// round 5
// speedup vs baseline: 4.0557x; 1.9208x over previous
#include <cuda_runtime.h>
#include <cuda_bf16.h>
#include <cstdint>

#define SEQ 2048
#define DIM 1024
#define NHEAD 16
#define DHEAD 64
#define QKV_N (3 * DIM)   // 3072

// ---------------------------------------------------------------------------
// Scratch (device globals — allocation-free rule)
// ---------------------------------------------------------------------------
__device__ __nv_bfloat16 g_x_hi[SEQ * DIM];
__device__ __nv_bfloat16 g_x_lo[SEQ * DIM];
__device__ __nv_bfloat16 g_wqkv_hi[QKV_N * DIM];   // [N,K] transposed
__device__ __nv_bfloat16 g_wqkv_lo[QKV_N * DIM];
__device__ __nv_bfloat16 g_wout_hi[DIM * DIM];     // [N,K] transposed
__device__ __nv_bfloat16 g_wout_lo[DIM * DIM];
__device__ __nv_bfloat16 g_qkv_hi[SEQ * QKV_N];
__device__ __nv_bfloat16 g_qkv_lo[SEQ * QKV_N];
__device__ __nv_bfloat16 g_attn_hi[SEQ * DIM];
__device__ __nv_bfloat16 g_attn_lo[SEQ * DIM];

// ---------------------------------------------------------------------------
// PTX helpers (baseline sm_80+ features only: mma.sync / ldmatrix / cp.async)
// ---------------------------------------------------------------------------
__device__ __forceinline__ uint32_t smem_u32(const void* p) {
    uint32_t a;
    asm("{ .reg .u64 t; cvta.to.shared.u64 t, %1; cvt.u32.u64 %0, t; }"
        : "=r"(a) : "l"(p));
    return a;
}

__device__ __forceinline__ void ldsm_x4(uint32_t* r, uint32_t addr) {
    asm volatile("ldmatrix.sync.aligned.m8n8.x4.shared.b16 {%0,%1,%2,%3}, [%4];"
                 : "=r"(r[0]), "=r"(r[1]), "=r"(r[2]), "=r"(r[3]) : "r"(addr));
}

__device__ __forceinline__ void ldsm_x4_t(uint32_t* r, uint32_t addr) {
    asm volatile("ldmatrix.sync.aligned.m8n8.x4.trans.shared.b16 {%0,%1,%2,%3}, [%4];"
                 : "=r"(r[0]), "=r"(r[1]), "=r"(r[2]), "=r"(r[3]) : "r"(addr));
}

__device__ __forceinline__ void mma_bf16(float* d, const uint32_t* a,
                                         const uint32_t* b) {
    asm volatile(
        "mma.sync.aligned.m16n8k16.row.col.f32.bf16.bf16.f32 "
        "{%0,%1,%2,%3}, {%4,%5,%6,%7}, {%8,%9}, {%0,%1,%2,%3};"
        : "+f"(d[0]), "+f"(d[1]), "+f"(d[2]), "+f"(d[3])
        : "r"(a[0]), "r"(a[1]), "r"(a[2]), "r"(a[3]), "r"(b[0]), "r"(b[1]));
}

__device__ __forceinline__ void cp16(uint32_t dst, const void* src) {
    asm volatile("cp.async.cg.shared.global [%0], [%1], 16;"
                 :: "r"(dst), "l"(src));
}
#define CP_WAIT_ALL() asm volatile("cp.async.wait_all;" ::: "memory")

// swizzled smem byte offset for (row, 16B-seg) in a 128B-row tile
#define SWZ(r, seg) ((uint32_t)((r) * 128 + (((seg) ^ ((r) & 7)) << 4)))

// pack 2 floats into bf16x2 hi + residual bf16x2 lo
__device__ __forceinline__ void split_pack(float x, float y,
                                           uint32_t& hi, uint32_t& lo) {
    __nv_bfloat162 h = __floats2bfloat162_rn(x, y);
    float2 hf = __bfloat1622float2(h);
    __nv_bfloat162 l = __floats2bfloat162_rn(x - hf.x, y - hf.y);
    hi = *reinterpret_cast<uint32_t*>(&h);
    lo = *reinterpret_cast<uint32_t*>(&l);
}

// ---------------------------------------------------------------------------
// Elementwise split: fp32 -> bf16 hi + bf16 lo
// ---------------------------------------------------------------------------
__global__ __launch_bounds__(256) void split_kernel(
    const float* __restrict__ in,
    __nv_bfloat16* __restrict__ hi, __nv_bfloat16* __restrict__ lo)
{
    int i = (blockIdx.x * 256 + threadIdx.x) * 4;
    float4 v = *(const float4*)(in + i);
    uint32_t h0, l0, h1, l1;
    split_pack(v.x, v.y, h0, l0);
    split_pack(v.z, v.w, h1, l1);
    *(uint32_t*)(hi + i)     = h0;
    *(uint32_t*)(hi + i + 2) = h1;
    *(uint32_t*)(lo + i)     = l0;
    *(uint32_t*)(lo + i + 2) = l1;
}

// ---------------------------------------------------------------------------
// Transpose + split: W[K,N] fp32 -> Wt[N,K] bf16 hi/lo. 32x32 tiles.
// ---------------------------------------------------------------------------
__global__ __launch_bounds__(256) void tsplit_kernel(
    const float* __restrict__ W,
    __nv_bfloat16* __restrict__ hi, __nv_bfloat16* __restrict__ lo,
    int K, int N)
{
    __shared__ float t[32][33];
    const int n0 = blockIdx.x * 32, k0 = blockIdx.y * 32;
    const int tx = threadIdx.x, ty = threadIdx.y;   // 32 x 8

    #pragma unroll
    for (int j = 0; j < 4; j++)
        t[ty + 8 * j][tx] = W[(size_t)(k0 + ty + 8 * j) * N + n0 + tx];
    __syncthreads();

    #pragma unroll
    for (int j = 0; j < 4; j++) {
        int row = ty + 8 * j;
        float v = t[tx][row];
        __nv_bfloat16 h = __float2bfloat16(v);
        size_t o = (size_t)(n0 + row) * K + k0 + tx;
        hi[o] = h;
        lo[o] = __float2bfloat16(v - __bfloat162float(h));
    }
}

// ---------------------------------------------------------------------------
// Split-bf16 tensor-core GEMM via mma.sync (3 terms, fp32 accum).
// Output either fp32 C (+bias) or bf16 hi/lo split (Chi/Clo non-null).
// ---------------------------------------------------------------------------
#define G_SMEM (4 * 16384)

__global__ __launch_bounds__(256, 2) void gemm_mma(
    const __nv_bfloat16* __restrict__ Ahi, const __nv_bfloat16* __restrict__ Alo,
    const __nv_bfloat16* __restrict__ Bhi, const __nv_bfloat16* __restrict__ Blo,
    float* __restrict__ C,
    __nv_bfloat16* __restrict__ Chi, __nv_bfloat16* __restrict__ Clo,
    int Mtot, int Ntot, int Ktot,
    const float* __restrict__ bias)
{
    extern __shared__ char smem[];
    const uint32_t sb = smem_u32(smem);
    const int tid  = threadIdx.x;
    const int wid  = tid >> 5;
    const int lane = tid & 31;
    const int row0 = blockIdx.y * 128, col0 = blockIdx.x * 128;

    const int m0 = (wid & 3) * 32;
    const int n0 = (wid >> 2) * 64;

    const uint32_t sA  = sb;
    const uint32_t sAL = sb + 16384;
    const uint32_t sB  = sb + 32768;
    const uint32_t sBL = sb + 49152;

    float acc[2][8][4] = {};

    const int nchunks = Ktot >> 6;
    for (int c = 0; c < nchunks; c++) {
        #pragma unroll
        for (int i = 0; i < 16; i++) {
            const int tile = i >> 2;
            int idx = tid + i * 256;
            int r   = (idx >> 3) & 127;
            int seg = idx & 7;
            const __nv_bfloat16* src;
            if (tile == 0)      src = Ahi + (size_t)(row0 + r) * Ktot;
            else if (tile == 1) src = Alo + (size_t)(row0 + r) * Ktot;
            else if (tile == 2) src = Bhi + (size_t)(col0 + r) * Ktot;
            else                src = Blo + (size_t)(col0 + r) * Ktot;
            cp16(sb + tile * 16384 + SWZ(r, seg), src + c * 64 + seg * 8);
        }
        CP_WAIT_ALL();
        __syncthreads();

        #pragma unroll
        for (int ks = 0; ks < 4; ks++) {
            uint32_t aH[2][4], aL[2][4];
            #pragma unroll
            for (int mt = 0; mt < 2; mt++) {
                int r   = m0 + mt * 16 + (lane & 15);
                int seg = ks * 2 + (lane >> 4);
                uint32_t off = SWZ(r, seg);
                ldsm_x4(aH[mt], sA  + off);
                ldsm_x4(aL[mt], sAL + off);
            }
            #pragma unroll
            for (int np = 0; np < 4; np++) {
                int nr  = n0 + np * 16 + ((lane >> 4) << 3) + (lane & 7);
                int seg = ks * 2 + ((lane >> 3) & 1);
                uint32_t off = SWZ(nr, seg);
                uint32_t bH[4], bL[4];
                ldsm_x4(bH, sB  + off);
                ldsm_x4(bL, sBL + off);
                #pragma unroll
                for (int mt = 0; mt < 2; mt++) {
                    mma_bf16(acc[mt][np * 2],     aH[mt], bH);
                    mma_bf16(acc[mt][np * 2 + 1], aH[mt], bH + 2);
                    mma_bf16(acc[mt][np * 2],     aH[mt], bL);
                    mma_bf16(acc[mt][np * 2 + 1], aH[mt], bL + 2);
                    mma_bf16(acc[mt][np * 2],     aL[mt], bH);
                    mma_bf16(acc[mt][np * 2 + 1], aL[mt], bH + 2);
                }
            }
        }
        __syncthreads();
    }

    #pragma unroll
    for (int mt = 0; mt < 2; mt++) {
        int r = row0 + m0 + mt * 16 + (lane >> 2);
        #pragma unroll
        for (int nt = 0; nt < 8; nt++) {
            int cc = col0 + n0 + nt * 8 + (lane & 3) * 2;
            float bx = 0.f, by = 0.f;
            if (bias) { bx = bias[cc]; by = bias[cc + 1]; }
            float v0x = acc[mt][nt][0] + bx, v0y = acc[mt][nt][1] + by;
            float v1x = acc[mt][nt][2] + bx, v1y = acc[mt][nt][3] + by;
            if (Chi) {
                uint32_t h0, l0, h1, l1;
                split_pack(v0x, v0y, h0, l0);
                split_pack(v1x, v1y, h1, l1);
                *(uint32_t*)&Chi[(size_t)r * Ntot + cc]       = h0;
                *(uint32_t*)&Clo[(size_t)r * Ntot + cc]       = l0;
                *(uint32_t*)&Chi[(size_t)(r + 8) * Ntot + cc] = h1;
                *(uint32_t*)&Clo[(size_t)(r + 8) * Ntot + cc] = l1;
            } else {
                *(float2*)&C[(size_t)r * Ntot + cc]       = make_float2(v0x, v0y);
                *(float2*)&C[(size_t)(r + 8) * Ntot + cc] = make_float2(v1x, v1y);
            }
        }
    }
}

// ---------------------------------------------------------------------------
// Flash attention via mma.sync, split-bf16 (3 terms on QK^T and PV).
// CTA = 128 threads (4 warps), 64-query tile, 64-key steps.
// grid = (SEQ/64, NHEAD). smem 48KB: Q/K/V hi+lo, SWZ128 layout.
// ---------------------------------------------------------------------------
#define AT_SMEM 49152

__global__ __launch_bounds__(128, 3) void attn_mma(
    const __nv_bfloat16* __restrict__ qkv_hi,
    const __nv_bfloat16* __restrict__ qkv_lo,
    __nv_bfloat16* __restrict__ out_hi,
    __nv_bfloat16* __restrict__ out_lo)
{
    extern __shared__ char smem[];
    const uint32_t sb = smem_u32(smem);
    const uint32_t sQh = sb,         sQl = sb + 8192;
    const uint32_t sKh = sb + 16384, sKl = sb + 24576;
    const uint32_t sVh = sb + 32768, sVl = sb + 40960;

    const int tid = threadIdx.x, wid = tid >> 5, lane = tid & 31;
    const int qb = blockIdx.x, h = blockIdx.y;
    const int q0 = qb * 64, hoff = h * DHEAD;

    // Q hi/lo: 64 rows x 64 bf16
    #pragma unroll
    for (int i = 0; i < 4; i++) {
        int idx = tid + i * 128;
        int r = idx >> 3, seg = idx & 7;
        size_t g = (size_t)(q0 + r) * QKV_N + hoff + seg * 8;
        cp16(sQh + SWZ(r, seg), qkv_hi + g);
        cp16(sQl + SWZ(r, seg), qkv_lo + g);
    }

    float o[8][4] = {};
    float m_i[2] = {-1e30f, -1e30f};
    float l_i[2] = {0.f, 0.f};

    const int rA = q0 + wid * 16 + (lane >> 2);

    for (int kt = 0; kt <= qb; kt++) {
        const int k0 = kt * 64;

        #pragma unroll
        for (int i = 0; i < 4; i++) {
            int idx = tid + i * 128;
            int r = idx >> 3, seg = idx & 7;
            size_t g = (size_t)(k0 + r) * QKV_N + DIM + hoff + seg * 8;
            cp16(sKh + SWZ(r, seg), qkv_hi + g);
            cp16(sKl + SWZ(r, seg), qkv_lo + g);
            cp16(sVh + SWZ(r, seg), qkv_hi + g + DIM);
            cp16(sVl + SWZ(r, seg), qkv_lo + g + DIM);
        }
        CP_WAIT_ALL();
        __syncthreads();

        // ---- S = Q K^T (3-term split) ----
        float s[8][4] = {};
        #pragma unroll
        for (int ks = 0; ks < 4; ks++) {
            uint32_t aH[4], aL[4];
            {
                int r   = wid * 16 + (lane & 15);
                int seg = ks * 2 + (lane >> 4);
                ldsm_x4(aH, sQh + SWZ(r, seg));
                ldsm_x4(aL, sQl + SWZ(r, seg));
            }
            #pragma unroll
            for (int np = 0; np < 4; np++) {
                int nr = np * 16 + ((lane >> 4) << 3) + (lane & 7);
                int sg = ks * 2 + ((lane >> 3) & 1);
                uint32_t off = SWZ(nr, sg);
                uint32_t bH[4], bL[4];
                ldsm_x4(bH, sKh + off);
                ldsm_x4(bL, sKl + off);
                mma_bf16(s[np * 2],     aH, bH);
                mma_bf16(s[np * 2 + 1], aH, bH + 2);
                mma_bf16(s[np * 2],     aH, bL);
                mma_bf16(s[np * 2 + 1], aH, bL + 2);
                mma_bf16(s[np * 2],     aL, bH);
                mma_bf16(s[np * 2 + 1], aL, bH + 2);
            }
        }

        // ---- scale + causal mask ----
        #pragma unroll
        for (int j = 0; j < 8; j++) {
            s[j][0] *= 0.125f; s[j][1] *= 0.125f;
            s[j][2] *= 0.125f; s[j][3] *= 0.125f;
        }
        if (kt == qb) {
            #pragma unroll
            for (int j = 0; j < 8; j++) {
                int col = k0 + j * 8 + (lane & 3) * 2;
                if (col > rA)         s[j][0] = -1e30f;
                if (col + 1 > rA)     s[j][1] = -1e30f;
                if (col > rA + 8)     s[j][2] = -1e30f;
                if (col + 1 > rA + 8) s[j][3] = -1e30f;
            }
        }

        // ---- online softmax on register fragments ----
        float mxA = -1e30f, mxB = -1e30f;
        #pragma unroll
        for (int j = 0; j < 8; j++) {
            mxA = fmaxf(mxA, fmaxf(s[j][0], s[j][1]));
            mxB = fmaxf(mxB, fmaxf(s[j][2], s[j][3]));
        }
        mxA = fmaxf(mxA, __shfl_xor_sync(0xffffffffu, mxA, 1));
        mxA = fmaxf(mxA, __shfl_xor_sync(0xffffffffu, mxA, 2));
        mxB = fmaxf(mxB, __shfl_xor_sync(0xffffffffu, mxB, 1));
        mxB = fmaxf(mxB, __shfl_xor_sync(0xffffffffu, mxB, 2));

        float mA = fmaxf(m_i[0], mxA), mB = fmaxf(m_i[1], mxB);
        float scA = __expf(m_i[0] - mA), scB = __expf(m_i[1] - mB);
        float lA = 0.f, lB = 0.f;
        #pragma unroll
        for (int j = 0; j < 8; j++) {
            s[j][0] = __expf(s[j][0] - mA);
            s[j][1] = __expf(s[j][1] - mA);
            s[j][2] = __expf(s[j][2] - mB);
            s[j][3] = __expf(s[j][3] - mB);
            lA += s[j][0] + s[j][1];
            lB += s[j][2] + s[j][3];
        }
        lA += __shfl_xor_sync(0xffffffffu, lA, 1);
        lA += __shfl_xor_sync(0xffffffffu, lA, 2);
        lB += __shfl_xor_sync(0xffffffffu, lB, 1);
        lB += __shfl_xor_sync(0xffffffffu, lB, 2);
        l_i[0] = l_i[0] * scA + lA;  m_i[0] = mA;
        l_i[1] = l_i[1] * scB + lB;  m_i[1] = mB;
        #pragma unroll
        for (int j = 0; j < 8; j++) {
            o[j][0] *= scA; o[j][1] *= scA;
            o[j][2] *= scB; o[j][3] *= scB;
        }

        // ---- O += P V (3-term split; P packed from C-frags, V via ldsm.trans) ----
        #pragma unroll
        for (int t = 0; t < 4; t++) {
            uint32_t pH[4], pL[4];
            split_pack(s[2 * t][0],     s[2 * t][1],     pH[0], pL[0]);
            split_pack(s[2 * t][2],     s[2 * t][3],     pH[1], pL[1]);
            split_pack(s[2 * t + 1][0], s[2 * t + 1][1], pH[2], pL[2]);
            split_pack(s[2 * t + 1][2], s[2 * t + 1][3], pH[3], pL[3]);
            #pragma unroll
            for (int sp = 0; sp < 4; sp++) {
                int g  = lane >> 3, rr = lane & 7;
                uint32_t off = SWZ(t * 16 + rr + ((g & 1) << 3),
                                   sp * 2 + (g >> 1));
                uint32_t bH[4], bL[4];
                ldsm_x4_t(bH, sVh + off);
                ldsm_x4_t(bL, sVl + off);
                mma_bf16(o[sp * 2],     pH, bH);
                mma_bf16(o[sp * 2 + 1], pH, bH + 2);
                mma_bf16(o[sp * 2],     pH, bL);
                mma_bf16(o[sp * 2 + 1], pH, bL + 2);
                mma_bf16(o[sp * 2],     pL, bH);
                mma_bf16(o[sp * 2 + 1], pL, bH + 2);
            }
        }
        __syncthreads();
    }

    // ---- epilogue: normalize, write split bf16 ----
    float invA = 1.0f / l_i[0], invB = 1.0f / l_i[1];
    #pragma unroll
    for (int j = 0; j < 8; j++) {
        int d = hoff + j * 8 + (lane & 3) * 2;
        uint32_t hA, lA2, hB, lB2;
        split_pack(o[j][0] * invA, o[j][1] * invA, hA, lA2);
        split_pack(o[j][2] * invB, o[j][3] * invB, hB, lB2);
        *(uint32_t*)&out_hi[(size_t)rA * DIM + d]       = hA;
        *(uint32_t*)&out_lo[(size_t)rA * DIM + d]       = lA2;
        *(uint32_t*)&out_hi[(size_t)(rA + 8) * DIM + d] = hB;
        *(uint32_t*)&out_lo[(size_t)(rA + 8) * DIM + d] = lB2;
    }
}

// ---------------------------------------------------------------------------
extern "C" void kernel_launch(void* const* d_in, const int* in_sizes, int n_in,
                              void* d_out, int out_size)
{
    const float* x    = (const float*)d_in[0];
    const float* Wqkv = (const float*)d_in[1];
    const float* Wout = (const float*)d_in[2];
    const float* bias = (const float*)d_in[3];
    float* out = (float*)d_out;

    __nv_bfloat16 *xh, *xl, *wqh, *wql, *woh, *wol, *qh, *ql, *ah, *al;
    cudaGetSymbolAddress((void**)&xh,  g_x_hi);
    cudaGetSymbolAddress((void**)&xl,  g_x_lo);
    cudaGetSymbolAddress((void**)&wqh, g_wqkv_hi);
    cudaGetSymbolAddress((void**)&wql, g_wqkv_lo);
    cudaGetSymbolAddress((void**)&woh, g_wout_hi);
    cudaGetSymbolAddress((void**)&wol, g_wout_lo);
    cudaGetSymbolAddress((void**)&qh,  g_qkv_hi);
    cudaGetSymbolAddress((void**)&ql,  g_qkv_lo);
    cudaGetSymbolAddress((void**)&ah,  g_attn_hi);
    cudaGetSymbolAddress((void**)&al,  g_attn_lo);

    cudaFuncSetAttribute(gemm_mma, cudaFuncAttributeMaxDynamicSharedMemorySize,
                         G_SMEM);
    cudaFuncSetAttribute(attn_mma, cudaFuncAttributeMaxDynamicSharedMemorySize,
                         AT_SMEM);

    // Prep: split x, transpose+split weights
    split_kernel<<<SEQ * DIM / 1024, 256>>>(x, xh, xl);
    tsplit_kernel<<<dim3(QKV_N / 32, DIM / 32), dim3(32, 8)>>>(Wqkv, wqh, wql,
                                                               DIM, QKV_N);
    tsplit_kernel<<<dim3(DIM / 32, DIM / 32), dim3(32, 8)>>>(Wout, woh, wol,
                                                             DIM, DIM);

    // 1) qkv = x @ Wqkv  -> bf16 hi/lo directly
    gemm_mma<<<dim3(QKV_N / 128, SEQ / 128), 256, G_SMEM>>>(
        xh, xl, wqh, wql, nullptr, qh, ql, SEQ, QKV_N, DIM, nullptr);

    // 2) attention -> bf16 hi/lo directly
    attn_mma<<<dim3(SEQ / 64, NHEAD), 128, AT_SMEM>>>(qh, ql, ah, al);

    // 3) out = attn @ Wout + bias  (fp32 output)
    gemm_mma<<<dim3(DIM / 128, SEQ / 128), 256, G_SMEM>>>(
        ah, al, woh, wol, out, nullptr, nullptr, SEQ, DIM, DIM, bias);
}